// round 2
// baseline (speedup 1.0000x reference)
#include <cuda_runtime.h>
#include <cuda_bf16.h>
#include <math.h>

// Problem constants
#define BATCH 1024
#define SEQ   80
#define UNITS 512
#define EMB   100
#define EMBP  112          // padded embedding dim (multiple of 16)
#define N4    2048         // 4 * UNITS
#define ROWS  (SEQ * BATCH)  // 81920

// ---------------- static device scratch (no allocations allowed) ----------------
__device__ float g_X[(size_t)ROWS * EMBP];        // gathered (padded) embeddings, row = t*BATCH+b
__device__ float g_Z1[(size_t)ROWS * N4];         // precomputed x@W1 + b1 (reordered cols)
__device__ float g_W1r[EMBP * N4];                // W1 reordered + zero padded rows
__device__ float g_U1r[UNITS * N4];               // U1 reordered
__device__ float g_Wr[(2 * UNITS) * N4];          // [W2; U2] reordered
__device__ float g_b1r[N4];
__device__ float g_b2r[N4];
__device__ float g_h1[2][(size_t)BATCH * UNITS];
__device__ float g_h2[2][(size_t)BATCH * UNITS];
__device__ float g_c1[(size_t)BATCH * UNITS];
__device__ float g_c2[(size_t)BATCH * UNITS];

__device__ __forceinline__ float sigmoidf_(float x) { return 1.0f / (1.0f + expf(-x)); }

// ---------------- init: zero initial states ----------------
__global__ void zero_state_kernel() {
    size_t i = (size_t)blockIdx.x * blockDim.x + threadIdx.x;
    if (i < (size_t)BATCH * UNITS) {
        g_h1[0][i] = 0.f;
        g_h2[0][i] = 0.f;
        g_c1[i] = 0.f;
        g_c2[i] = 0.f;
    }
}

// ---------------- prepack: reorder weights so col n = unit*4 + gate ----------------
// original z layout: gate g occupies columns [g*512, (g+1)*512); reorder to u*4+g.
__global__ void prepack_kernel(const float* __restrict__ W1, const float* __restrict__ U1,
                               const float* __restrict__ b1, const float* __restrict__ W2,
                               const float* __restrict__ U2, const float* __restrict__ b2) {
    int n = blockIdx.x;                 // 0..2047
    int u = n >> 2;
    int gg = n & 3;
    int src = gg * UNITS + u;           // source column in [0,2048)
    for (int k = threadIdx.x; k < 2 * UNITS; k += blockDim.x) {
        if (k < UNITS)
            g_U1r[k * N4 + n] = U1[(size_t)k * N4 + src];
        g_Wr[k * N4 + n] = (k < UNITS) ? W2[(size_t)k * N4 + src]
                                       : U2[(size_t)(k - UNITS) * N4 + src];
        if (k < EMBP)
            g_W1r[k * N4 + n] = (k < EMB) ? W1[(size_t)k * N4 + src] : 0.f;
    }
    if (threadIdx.x == 0) {
        g_b1r[n] = b1[src];
        g_b2r[n] = b2[src];
    }
}

// ---------------- embedding gather (time-major rows, zero-padded to EMBP) ----------------
__global__ void gather_kernel(const int* __restrict__ tokens, const float* __restrict__ emb) {
    int row = blockIdx.x;               // t*BATCH + b
    int t = row / BATCH;
    int b = row - t * BATCH;
    int tok = tokens[(size_t)b * SEQ + t];
    int e = threadIdx.x;
    if (e < EMBP) {
        g_X[(size_t)row * EMBP + e] = (e < EMB) ? emb[(size_t)tok * EMB + e] : 0.f;
    }
}

// ---------------- big pre-GEMM: Z1 = X @ W1r + b1r ----------------
// grid (N4/128, ROWS/128), 256 threads, 128x128 tile, 8x8 microtile, BK=16
__global__ __launch_bounds__(256) void pregemm_kernel() {
    __shared__ float As[16][132];
    __shared__ float Bs[16][128];
    int tid = threadIdx.x;
    int mo = blockIdx.y * 128, no = blockIdx.x * 128;
    int tm = (tid >> 4) * 8, tn = (tid & 15) * 8;
    int ar = tid >> 2, ac = (tid & 3) * 4;
    int br = tid >> 5, bc = (tid & 31) * 4;

    float acc[8][8];
#pragma unroll
    for (int i = 0; i < 8; i++)
#pragma unroll
        for (int j = 0; j < 8; j++) acc[i][j] = 0.f;

    for (int k0 = 0; k0 < EMBP; k0 += 16) {
        float4 a0 = *(const float4*)(g_X + (size_t)(mo + ar) * EMBP + k0 + ac);
        float4 a1 = *(const float4*)(g_X + (size_t)(mo + ar + 64) * EMBP + k0 + ac);
        As[ac + 0][ar] = a0.x; As[ac + 1][ar] = a0.y; As[ac + 2][ar] = a0.z; As[ac + 3][ar] = a0.w;
        As[ac + 0][ar + 64] = a1.x; As[ac + 1][ar + 64] = a1.y; As[ac + 2][ar + 64] = a1.z; As[ac + 3][ar + 64] = a1.w;
        *(float4*)&Bs[br][bc]     = *(const float4*)(g_W1r + (size_t)(k0 + br) * N4 + no + bc);
        *(float4*)&Bs[br + 8][bc] = *(const float4*)(g_W1r + (size_t)(k0 + br + 8) * N4 + no + bc);
        __syncthreads();
#pragma unroll
        for (int kk = 0; kk < 16; kk++) {
            float av[8], bv[8];
#pragma unroll
            for (int i = 0; i < 8; i++) av[i] = As[kk][tm + i];
#pragma unroll
            for (int j = 0; j < 8; j++) bv[j] = Bs[kk][tn + j];
#pragma unroll
            for (int i = 0; i < 8; i++)
#pragma unroll
                for (int j = 0; j < 8; j++) acc[i][j] += av[i] * bv[j];
        }
        __syncthreads();
    }
#pragma unroll
    for (int i = 0; i < 8; i++) {
        size_t row = (size_t)(mo + tm + i);
#pragma unroll
        for (int j = 0; j < 8; j++) {
            g_Z1[row * N4 + no + tn + j] = acc[i][j] + g_b1r[no + tn + j];
        }
    }
}

// ---------------- per-step layer-1: z = Z1[t] + h1@U1r ; gates; update h1,c1 ----------------
// grid (16, 8), 256 threads
__global__ __launch_bounds__(256) void lstm1_kernel(int t) {
    const float* __restrict__ A = g_h1[t & 1];
    const float* __restrict__ zpre = g_Z1 + (size_t)t * BATCH * N4;
    float* __restrict__ hout = g_h1[(t + 1) & 1];

    __shared__ float As[16][132];
    __shared__ float Bs[16][128];
    int tid = threadIdx.x;
    int mo = blockIdx.y * 128, no = blockIdx.x * 128;
    int tm = (tid >> 4) * 8, tn = (tid & 15) * 8;
    int ar = tid >> 2, ac = (tid & 3) * 4;
    int br = tid >> 5, bc = (tid & 31) * 4;

    float acc[8][8];
#pragma unroll
    for (int i = 0; i < 8; i++)
#pragma unroll
        for (int j = 0; j < 8; j++) acc[i][j] = 0.f;

    for (int k0 = 0; k0 < UNITS; k0 += 16) {
        float4 a0 = *(const float4*)(A + (size_t)(mo + ar) * UNITS + k0 + ac);
        float4 a1 = *(const float4*)(A + (size_t)(mo + ar + 64) * UNITS + k0 + ac);
        As[ac + 0][ar] = a0.x; As[ac + 1][ar] = a0.y; As[ac + 2][ar] = a0.z; As[ac + 3][ar] = a0.w;
        As[ac + 0][ar + 64] = a1.x; As[ac + 1][ar + 64] = a1.y; As[ac + 2][ar + 64] = a1.z; As[ac + 3][ar + 64] = a1.w;
        *(float4*)&Bs[br][bc]     = *(const float4*)(g_U1r + (size_t)(k0 + br) * N4 + no + bc);
        *(float4*)&Bs[br + 8][bc] = *(const float4*)(g_U1r + (size_t)(k0 + br + 8) * N4 + no + bc);
        __syncthreads();
#pragma unroll
        for (int kk = 0; kk < 16; kk++) {
            float av[8], bv[8];
#pragma unroll
            for (int i = 0; i < 8; i++) av[i] = As[kk][tm + i];
#pragma unroll
            for (int j = 0; j < 8; j++) bv[j] = Bs[kk][tn + j];
#pragma unroll
            for (int i = 0; i < 8; i++)
#pragma unroll
                for (int j = 0; j < 8; j++) acc[i][j] += av[i] * bv[j];
        }
        __syncthreads();
    }

    // fused LSTM gate epilogue: 8 consecutive n-cols = 2 units (n = u*4 + gate)
#pragma unroll
    for (int i = 0; i < 8; i++) {
        int row = mo + tm + i;
        const float* zp = zpre + (size_t)row * N4 + no + tn;
#pragma unroll
        for (int uu = 0; uu < 2; uu++) {
            float zi = acc[i][uu * 4 + 0] + zp[uu * 4 + 0];
            float zf = acc[i][uu * 4 + 1] + zp[uu * 4 + 1];
            float zg = acc[i][uu * 4 + 2] + zp[uu * 4 + 2];
            float zo = acc[i][uu * 4 + 3] + zp[uu * 4 + 3];
            int u = ((no + tn) >> 2) + uu;
            size_t idx = (size_t)row * UNITS + u;
            float cn = sigmoidf_(zf) * g_c1[idx] + sigmoidf_(zi) * tanhf(zg);
            g_c1[idx] = cn;
            hout[idx] = sigmoidf_(zo) * tanhf(cn);
        }
    }
}

// ---------------- per-step layer-2: z = [h1_new | h2_old] @ Wr + b2r ; update h2,c2 ----------------
__global__ __launch_bounds__(256) void lstm2_kernel(int t) {
    const float* __restrict__ A0 = g_h1[(t + 1) & 1];  // fresh h1 (k 0..511)
    const float* __restrict__ A1 = g_h2[t & 1];        // old h2   (k 512..1023)
    float* __restrict__ hout = g_h2[(t + 1) & 1];

    __shared__ float As[16][132];
    __shared__ float Bs[16][128];
    int tid = threadIdx.x;
    int mo = blockIdx.y * 128, no = blockIdx.x * 128;
    int tm = (tid >> 4) * 8, tn = (tid & 15) * 8;
    int ar = tid >> 2, ac = (tid & 3) * 4;
    int br = tid >> 5, bc = (tid & 31) * 4;

    float acc[8][8];
#pragma unroll
    for (int i = 0; i < 8; i++)
#pragma unroll
        for (int j = 0; j < 8; j++) acc[i][j] = 0.f;

    for (int k0 = 0; k0 < 2 * UNITS; k0 += 16) {
        const float* A = (k0 < UNITS) ? A0 : A1;
        int kk0 = k0 & (UNITS - 1);
        float4 a0 = *(const float4*)(A + (size_t)(mo + ar) * UNITS + kk0 + ac);
        float4 a1 = *(const float4*)(A + (size_t)(mo + ar + 64) * UNITS + kk0 + ac);
        As[ac + 0][ar] = a0.x; As[ac + 1][ar] = a0.y; As[ac + 2][ar] = a0.z; As[ac + 3][ar] = a0.w;
        As[ac + 0][ar + 64] = a1.x; As[ac + 1][ar + 64] = a1.y; As[ac + 2][ar + 64] = a1.z; As[ac + 3][ar + 64] = a1.w;
        *(float4*)&Bs[br][bc]     = *(const float4*)(g_Wr + (size_t)(k0 + br) * N4 + no + bc);
        *(float4*)&Bs[br + 8][bc] = *(const float4*)(g_Wr + (size_t)(k0 + br + 8) * N4 + no + bc);
        __syncthreads();
#pragma unroll
        for (int kk = 0; kk < 16; kk++) {
            float av[8], bv[8];
#pragma unroll
            for (int i = 0; i < 8; i++) av[i] = As[kk][tm + i];
#pragma unroll
            for (int j = 0; j < 8; j++) bv[j] = Bs[kk][tn + j];
#pragma unroll
            for (int i = 0; i < 8; i++)
#pragma unroll
                for (int j = 0; j < 8; j++) acc[i][j] += av[i] * bv[j];
        }
        __syncthreads();
    }

#pragma unroll
    for (int i = 0; i < 8; i++) {
        int row = mo + tm + i;
#pragma unroll
        for (int uu = 0; uu < 2; uu++) {
            int nb = no + tn + uu * 4;
            float zi = acc[i][uu * 4 + 0] + g_b2r[nb + 0];
            float zf = acc[i][uu * 4 + 1] + g_b2r[nb + 1];
            float zg = acc[i][uu * 4 + 2] + g_b2r[nb + 2];
            float zo = acc[i][uu * 4 + 3] + g_b2r[nb + 3];
            int u = nb >> 2;
            size_t idx = (size_t)row * UNITS + u;
            float cn = sigmoidf_(zf) * g_c2[idx] + sigmoidf_(zi) * tanhf(zg);
            g_c2[idx] = cn;
            hout[idx] = sigmoidf_(zo) * tanhf(cn);
        }
    }
}

// ---------------- output projection: out[b] = sigmoid(h2 . Wout + bout) ----------------
__global__ void out_kernel(const float* __restrict__ Wout, const float* __restrict__ bout,
                           float* __restrict__ out, int parity) {
    int gw = (blockIdx.x * blockDim.x + threadIdx.x) >> 5;   // warp id = batch row
    int lane = threadIdx.x & 31;
    if (gw >= BATCH) return;
    const float* h = g_h2[parity] + (size_t)gw * UNITS;
    float s = 0.f;
    for (int k = lane; k < UNITS; k += 32) s += h[k] * Wout[k];
#pragma unroll
    for (int off = 16; off > 0; off >>= 1) s += __shfl_xor_sync(0xFFFFFFFF, s, off);
    if (lane == 0) out[gw] = sigmoidf_(s + bout[0]);
}

// ---------------- launch ----------------
extern "C" void kernel_launch(void* const* d_in, const int* in_sizes, int n_in,
                              void* d_out, int out_size) {
    const int*   tokens = (const int*)d_in[0];
    const float* emb    = (const float*)d_in[1];
    const float* W1     = (const float*)d_in[2];
    const float* U1     = (const float*)d_in[3];
    const float* b1     = (const float*)d_in[4];
    const float* W2     = (const float*)d_in[5];
    const float* U2     = (const float*)d_in[6];
    const float* b2     = (const float*)d_in[7];
    const float* Wout   = (const float*)d_in[8];
    const float* bout   = (const float*)d_in[9];
    float* out = (float*)d_out;

    zero_state_kernel<<<(BATCH * UNITS + 255) / 256, 256>>>();
    prepack_kernel<<<N4, 256>>>(W1, U1, b1, W2, U2, b2);
    gather_kernel<<<ROWS, 128>>>(tokens, emb);
    pregemm_kernel<<<dim3(N4 / 128, ROWS / 128), 256>>>();

    for (int t = 0; t < SEQ; t++) {
        lstm1_kernel<<<dim3(N4 / 128, BATCH / 128), 256>>>(t);
        lstm2_kernel<<<dim3(N4 / 128, BATCH / 128), 256>>>(t);
    }
    out_kernel<<<(BATCH * 32 + 255) / 256, 256>>>(Wout, bout, out, SEQ & 1);
}

// round 5
// speedup vs baseline: 2.0016x; 2.0016x over previous
#include <cuda_runtime.h>
#include <cuda_bf16.h>
#include <math.h>
#include <stdint.h>

// Problem constants
#define BATCH 1024
#define SEQ   80
#define UNITS 512
#define EMB   100
#define EMBP  112
#define N4    2048
#define ROWS  (SEQ * BATCH)
#define KC    64              // K-chunk (64 bf16 = 128B rows)

// ---------------- static device scratch ----------------
__device__ float g_X[(size_t)ROWS * EMBP];
__device__ float g_Z1[(size_t)ROWS * N4];          // x@W1 + b1 (reordered cols)
__device__ float g_W1r[EMBP * N4];
__device__ float g_b1r[N4];
__device__ float g_b2r[N4];
// split-bf16 weights, [N][K] K-major (B operand for mma row.col)
__device__ __nv_bfloat16 g_U1hi[(size_t)N4 * UNITS];
__device__ __nv_bfloat16 g_U1lo[(size_t)N4 * UNITS];
__device__ __nv_bfloat16 g_W2hi[(size_t)N4 * 2 * UNITS];
__device__ __nv_bfloat16 g_W2lo[(size_t)N4 * 2 * UNITS];
__device__ float g_h1[2][(size_t)BATCH * UNITS];
__device__ float g_h2[2][(size_t)BATCH * UNITS];
__device__ float g_c1[(size_t)BATCH * UNITS];
__device__ float g_c2[(size_t)BATCH * UNITS];

__device__ __forceinline__ float sigmoidf_(float x) { return 1.0f / (1.0f + expf(-x)); }

__device__ __forceinline__ uint32_t smem_u32(const void* p) {
    uint32_t a;
    asm("{ .reg .u64 t; cvta.to.shared.u64 t, %1; cvt.u32.u64 %0, t; }" : "=r"(a) : "l"(p));
    return a;
}
__device__ __forceinline__ uint32_t sw_off(uint32_t off) {
    return off ^ ((off >> 3) & 0x70);
}
__device__ __forceinline__ void ldmatrix_x4(uint32_t* r, uint32_t addr) {
    asm volatile("ldmatrix.sync.aligned.m8n8.x4.shared.b16 {%0,%1,%2,%3}, [%4];"
                 : "=r"(r[0]), "=r"(r[1]), "=r"(r[2]), "=r"(r[3]) : "r"(addr));
}
__device__ __forceinline__ void mma16816(float* c, const uint32_t* a, const uint32_t* b) {
    asm volatile("mma.sync.aligned.m16n8k16.row.col.f32.bf16.bf16.f32 "
                 "{%0,%1,%2,%3}, {%4,%5,%6,%7}, {%8,%9}, {%0,%1,%2,%3};"
                 : "+f"(c[0]), "+f"(c[1]), "+f"(c[2]), "+f"(c[3])
                 : "r"(a[0]), "r"(a[1]), "r"(a[2]), "r"(a[3]), "r"(b[0]), "r"(b[1]));
}
__device__ __forceinline__ void cp_async16(uint32_t dst, const void* src) {
    asm volatile("cp.async.cg.shared.global [%0], [%1], 16;" :: "r"(dst), "l"(src) : "memory");
}
#define CP_COMMIT() asm volatile("cp.async.commit_group;" ::: "memory")
#define CP_WAIT0()  asm volatile("cp.async.wait_group 0;" ::: "memory")

// ---------------- init states ----------------
__global__ void zero_state_kernel() {
    size_t i = (size_t)blockIdx.x * blockDim.x + threadIdx.x;
    if (i < (size_t)BATCH * UNITS) {
        g_h1[0][i] = 0.f; g_h2[0][i] = 0.f; g_c1[i] = 0.f; g_c2[i] = 0.f;
    }
}

// ---------------- prepack: reorder (n = u*4+g) + bf16 hi/lo split, [N][K] ----------------
__global__ void prepack_kernel(const float* __restrict__ W1, const float* __restrict__ U1,
                               const float* __restrict__ b1, const float* __restrict__ W2,
                               const float* __restrict__ U2, const float* __restrict__ b2) {
    int n = blockIdx.x;
    int u = n >> 2, gg = n & 3;
    int src = gg * UNITS + u;
    for (int k = threadIdx.x; k < 2 * UNITS; k += blockDim.x) {
        float w = (k < UNITS) ? W2[(size_t)k * N4 + src] : U2[(size_t)(k - UNITS) * N4 + src];
        __nv_bfloat16 hi = __float2bfloat16(w);
        g_W2hi[(size_t)n * (2 * UNITS) + k] = hi;
        g_W2lo[(size_t)n * (2 * UNITS) + k] = __float2bfloat16(w - __bfloat162float(hi));
        if (k < UNITS) {
            float v = U1[(size_t)k * N4 + src];
            __nv_bfloat16 h = __float2bfloat16(v);
            g_U1hi[(size_t)n * UNITS + k] = h;
            g_U1lo[(size_t)n * UNITS + k] = __float2bfloat16(v - __bfloat162float(h));
        }
        if (k < EMBP)
            g_W1r[k * N4 + n] = (k < EMB) ? W1[(size_t)k * N4 + src] : 0.f;
    }
    if (threadIdx.x == 0) { g_b1r[n] = b1[src]; g_b2r[n] = b2[src]; }
}

// ---------------- embedding gather ----------------
__global__ void gather_kernel(const int* __restrict__ tokens, const float* __restrict__ emb) {
    int row = blockIdx.x;
    int t = row / BATCH, b = row - t * BATCH;
    int tok = tokens[(size_t)b * SEQ + t];
    int e = threadIdx.x;
    if (e < EMBP)
        g_X[(size_t)row * EMBP + e] = (e < EMB) ? emb[(size_t)tok * EMB + e] : 0.f;
}

// ---------------- pre-GEMM: Z1 = X @ W1r + b1r (fp32 SIMT) ----------------
__global__ __launch_bounds__(256) void pregemm_kernel() {
    __shared__ float As[16][132];
    __shared__ float Bs[16][128];
    int tid = threadIdx.x;
    int mo = blockIdx.y * 128, no = blockIdx.x * 128;
    int tm = (tid >> 4) * 8, tn = (tid & 15) * 8;
    int ar = tid >> 2, ac = (tid & 3) * 4;
    int br = tid >> 5, bc = (tid & 31) * 4;
    float acc[8][8];
#pragma unroll
    for (int i = 0; i < 8; i++)
#pragma unroll
        for (int j = 0; j < 8; j++) acc[i][j] = 0.f;
    for (int k0 = 0; k0 < EMBP; k0 += 16) {
        float4 a0 = *(const float4*)(g_X + (size_t)(mo + ar) * EMBP + k0 + ac);
        float4 a1 = *(const float4*)(g_X + (size_t)(mo + ar + 64) * EMBP + k0 + ac);
        As[ac + 0][ar] = a0.x; As[ac + 1][ar] = a0.y; As[ac + 2][ar] = a0.z; As[ac + 3][ar] = a0.w;
        As[ac + 0][ar + 64] = a1.x; As[ac + 1][ar + 64] = a1.y; As[ac + 2][ar + 64] = a1.z; As[ac + 3][ar + 64] = a1.w;
        *(float4*)&Bs[br][bc]     = *(const float4*)(g_W1r + (size_t)(k0 + br) * N4 + no + bc);
        *(float4*)&Bs[br + 8][bc] = *(const float4*)(g_W1r + (size_t)(k0 + br + 8) * N4 + no + bc);
        __syncthreads();
#pragma unroll
        for (int kk = 0; kk < 16; kk++) {
            float av[8], bv[8];
#pragma unroll
            for (int i = 0; i < 8; i++) av[i] = As[kk][tm + i];
#pragma unroll
            for (int j = 0; j < 8; j++) bv[j] = Bs[kk][tn + j];
#pragma unroll
            for (int i = 0; i < 8; i++)
#pragma unroll
                for (int j = 0; j < 8; j++) acc[i][j] += av[i] * bv[j];
        }
        __syncthreads();
    }
#pragma unroll
    for (int i = 0; i < 8; i++) {
        size_t row = (size_t)(mo + tm + i);
#pragma unroll
        for (int j = 0; j < 8; j++)
            g_Z1[row * N4 + no + tn + j] = acc[i][j] + g_b1r[no + tn + j];
    }
}

// ---------------- HMMA LSTM step (split-bf16 3-term + fused gates) ----------------
// grid (16, 8) = (N/128, M/128), 256 thr = 8 warps (2M x 4N), warp tile 64x32.
// SMEM stage (64KB): Ahi 16K | Alo 16K | Bhi 16K | Blo 16K. Double buffered.
#define STAGE_BYTES 65536
#define SMEM_DYN    (1024 + 2 * STAGE_BYTES)

template <int LAYER>
__global__ __launch_bounds__(256, 1) void lstm_mma_kernel(int t) {
    constexpr int K = (LAYER == 1) ? UNITS : 2 * UNITS;
    constexpr int NC = K / KC;   // 8 or 16

    extern __shared__ char dsm[];
    uint32_t raw = smem_u32(dsm);
    uint32_t pad = (1024u - (raw & 1023u)) & 1023u;
    char* sm = dsm + pad;
    uint32_t sb = raw + pad;

    int tid = threadIdx.x, wid = tid >> 5, lane = tid & 31;
    int wm = wid >> 2, wn = wid & 3;
    int no = blockIdx.x * 128, mo = blockIdx.y * 128;

    const float* A0;
    const float* A1 = nullptr;
    float* hout;
    float* cst;
    const __nv_bfloat16 *Bhi, *Blo;
    if (LAYER == 1) {
        A0 = g_h1[t & 1]; hout = g_h1[(t + 1) & 1]; cst = g_c1;
        Bhi = g_U1hi; Blo = g_U1lo;
    } else {
        A0 = g_h1[(t + 1) & 1]; A1 = g_h2[t & 1]; hout = g_h2[(t + 1) & 1]; cst = g_c2;
        Bhi = g_W2hi; Blo = g_W2lo;
    }

    float acc[4][4][4];
#pragma unroll
    for (int a = 0; a < 4; a++)
#pragma unroll
        for (int b = 0; b < 4; b++)
#pragma unroll
            for (int cc = 0; cc < 4; cc++) acc[a][b][cc] = 0.f;

    // per-thread A-load coords (8 float4 per chunk): v = tid + 256*j -> r = v>>4, q = v&15
    // per-thread B cp.async coords (4 x 16B hi + 4 lo): v = tid + 256*j -> r = v>>3, q = v&7

    // A store: registers held across mma section
    float4 areg[8];

    // ---- prologue: chunk 0 ----
    {
        const float* Asrc = A0;
#pragma unroll
        for (int j = 0; j < 8; j++) {
            int v = tid + 256 * j;
            int r = v >> 4, q = v & 15;
            areg[j] = *(const float4*)(Asrc + (size_t)(mo + r) * UNITS + q * 4);
        }
#pragma unroll
        for (int j = 0; j < 4; j++) {
            int v = tid + 256 * j;
            int r = v >> 3, q = v & 7;
            uint32_t off = sw_off((uint32_t)(r * 128 + q * 16));
            cp_async16(sb + 32768 + off, Bhi + (size_t)(no + r) * K + q * 8);
            cp_async16(sb + 49152 + off, Blo + (size_t)(no + r) * K + q * 8);
        }
        CP_COMMIT();
        // split-store A
#pragma unroll
        for (int j = 0; j < 8; j++) {
            int v = tid + 256 * j;
            int r = v >> 4, q = v & 15;
            float4 x = areg[j];
            __nv_bfloat162 h01 = __floats2bfloat162_rn(x.x, x.y);
            __nv_bfloat162 h23 = __floats2bfloat162_rn(x.z, x.w);
            __nv_bfloat162 l01 = __floats2bfloat162_rn(x.x - __bfloat162float(h01.x), x.y - __bfloat162float(h01.y));
            __nv_bfloat162 l23 = __floats2bfloat162_rn(x.z - __bfloat162float(h23.x), x.w - __bfloat162float(h23.y));
            uint32_t off = sw_off((uint32_t)(r * 128 + q * 8));
            *(uint2*)(sm + off)         = make_uint2(*(uint32_t*)&h01, *(uint32_t*)&h23);
            *(uint2*)(sm + 16384 + off) = make_uint2(*(uint32_t*)&l01, *(uint32_t*)&l23);
        }
        CP_WAIT0();
        __syncthreads();
    }

    // precompute ldmatrix lane-row offsets
    // A: lanes 0-15 -> rows l, kb 0; lanes 16-31 -> rows l-16, kb 16
    uint32_t a_rowoff[4];
#pragma unroll
    for (int mt = 0; mt < 4; mt++)
        a_rowoff[mt] = (uint32_t)((wm * 64 + mt * 16 + (lane & 15)) * 128 + (lane >> 4) * 16);
    // B: g = lane>>3; nrow = pair*16 + (g>>1)*8 + (lane&7); kb = (g&1)*16
    uint32_t b_rowoff[2];
#pragma unroll
    for (int pr = 0; pr < 2; pr++)
        b_rowoff[pr] = (uint32_t)((wn * 32 + pr * 16 + ((lane >> 4) & 1) * 8 + (lane & 7)) * 128 + ((lane >> 3) & 1) * 16);

    for (int i = 0; i < NC; i++) {
        uint32_t cur = sb + (uint32_t)(i & 1) * STAGE_BYTES;
        char* curp = sm + (i & 1) * STAGE_BYTES;
        uint32_t nxt = sb + (uint32_t)((i + 1) & 1) * STAGE_BYTES;
        char* nxtp = sm + ((i + 1) & 1) * STAGE_BYTES;

        // ---- prefetch chunk i+1 ----
        if (i + 1 < NC) {
            int k0 = (i + 1) * KC;
            const float* Asrc = (LAYER == 2 && k0 >= UNITS) ? A1 : A0;
            int kk0 = k0 & (UNITS - 1);
#pragma unroll
            for (int j = 0; j < 8; j++) {
                int v = tid + 256 * j;
                int r = v >> 4, q = v & 15;
                areg[j] = *(const float4*)(Asrc + (size_t)(mo + r) * UNITS + kk0 + q * 4);
            }
#pragma unroll
            for (int j = 0; j < 4; j++) {
                int v = tid + 256 * j;
                int r = v >> 3, q = v & 7;
                uint32_t off = sw_off((uint32_t)(r * 128 + q * 16));
                cp_async16(nxt + 32768 + off, Bhi + (size_t)(no + r) * K + k0 + q * 8);
                cp_async16(nxt + 49152 + off, Blo + (size_t)(no + r) * K + k0 + q * 8);
            }
            CP_COMMIT();
        }

        // ---- mma on current chunk ----
#pragma unroll
        for (int ks = 0; ks < 4; ks++) {
            uint32_t ahi[4][4], alo[4][4], bhi[2][4], blo[2][4];
#pragma unroll
            for (int mt = 0; mt < 4; mt++) {
                uint32_t off = sw_off(a_rowoff[mt] + ks * 32);
                ldmatrix_x4(ahi[mt], cur + off);
                ldmatrix_x4(alo[mt], cur + 16384 + off);
            }
#pragma unroll
            for (int pr = 0; pr < 2; pr++) {
                uint32_t off = sw_off(b_rowoff[pr] + ks * 32);
                ldmatrix_x4(bhi[pr], cur + 32768 + off);
                ldmatrix_x4(blo[pr], cur + 49152 + off);
            }
#pragma unroll
            for (int mt = 0; mt < 4; mt++)
#pragma unroll
                for (int nt = 0; nt < 4; nt++) {
                    const uint32_t* bh = &bhi[nt >> 1][(nt & 1) * 2];
                    const uint32_t* bl = &blo[nt >> 1][(nt & 1) * 2];
                    mma16816(acc[mt][nt], ahi[mt], bh);
                    mma16816(acc[mt][nt], ahi[mt], bl);
                    mma16816(acc[mt][nt], alo[mt], bh);
                }
        }

        // ---- store prefetched A ----
        if (i + 1 < NC) {
#pragma unroll
            for (int j = 0; j < 8; j++) {
                int v = tid + 256 * j;
                int r = v >> 4, q = v & 15;
                float4 x = areg[j];
                __nv_bfloat162 h01 = __floats2bfloat162_rn(x.x, x.y);
                __nv_bfloat162 h23 = __floats2bfloat162_rn(x.z, x.w);
                __nv_bfloat162 l01 = __floats2bfloat162_rn(x.x - __bfloat162float(h01.x), x.y - __bfloat162float(h01.y));
                __nv_bfloat162 l23 = __floats2bfloat162_rn(x.z - __bfloat162float(h23.x), x.w - __bfloat162float(h23.y));
                uint32_t off = sw_off((uint32_t)(r * 128 + q * 8));
                *(uint2*)(nxtp + off)         = make_uint2(*(uint32_t*)&h01, *(uint32_t*)&h23);
                *(uint2*)(nxtp + 16384 + off) = make_uint2(*(uint32_t*)&l01, *(uint32_t*)&l23);
            }
            CP_WAIT0();
        }
        __syncthreads();
        (void)curp;
    }

    // ---- fused LSTM gate epilogue ----
    // acc[mt][nt]: {r0c0, r0c1, r1c0, r1c1}; r0 = lane>>2, r1 = r0+8; c0 = (lane&3)*2.
    // even lanes hold (i,f), odd lanes hold (g,o) of the same unit -> shfl_xor(1).
#pragma unroll
    for (int mt = 0; mt < 4; mt++)
#pragma unroll
        for (int nt = 0; nt < 4; nt++)
#pragma unroll
            for (int ri = 0; ri < 2; ri++) {
                float v0 = acc[mt][nt][2 * ri + 0];
                float v1 = acc[mt][nt][2 * ri + 1];
                float o0 = __shfl_xor_sync(0xFFFFFFFF, v0, 1);
                float o1 = __shfl_xor_sync(0xFFFFFFFF, v1, 1);
                if ((lane & 1) == 0) {
                    int row = mo + wm * 64 + mt * 16 + (lane >> 2) + ri * 8;
                    int c_abs = no + wn * 32 + nt * 8 + (lane & 3) * 2;
                    const float* zp = (LAYER == 1)
                        ? (g_Z1 + (size_t)t * BATCH * N4 + (size_t)row * N4 + c_abs)
                        : (g_b2r + c_abs);
                    float4 zb = *(const float4*)zp;
                    float zi = v0 + zb.x, zf = v1 + zb.y;
                    float zg = o0 + zb.z, zo = o1 + zb.w;
                    int u = c_abs >> 2;
                    size_t idx = (size_t)row * UNITS + u;
                    float cn = sigmoidf_(zf) * cst[idx] + sigmoidf_(zi) * tanhf(zg);
                    cst[idx] = cn;
                    hout[idx] = sigmoidf_(zo) * tanhf(cn);
                }
            }
}

// ---------------- output projection ----------------
__global__ void out_kernel(const float* __restrict__ Wout, const float* __restrict__ bout,
                           float* __restrict__ out, int parity) {
    int gw = (blockIdx.x * blockDim.x + threadIdx.x) >> 5;
    int lane = threadIdx.x & 31;
    if (gw >= BATCH) return;
    const float* h = g_h2[parity] + (size_t)gw * UNITS;
    float s = 0.f;
    for (int k = lane; k < UNITS; k += 32) s += h[k] * Wout[k];
#pragma unroll
    for (int off = 16; off > 0; off >>= 1) s += __shfl_xor_sync(0xFFFFFFFF, s, off);
    if (lane == 0) out[gw] = sigmoidf_(s + bout[0]);
}

// ---------------- launch ----------------
extern "C" void kernel_launch(void* const* d_in, const int* in_sizes, int n_in,
                              void* d_out, int out_size) {
    const int*   tokens = (const int*)d_in[0];
    const float* emb    = (const float*)d_in[1];
    const float* W1     = (const float*)d_in[2];
    const float* U1     = (const float*)d_in[3];
    const float* b1     = (const float*)d_in[4];
    const float* W2     = (const float*)d_in[5];
    const float* U2     = (const float*)d_in[6];
    const float* b2     = (const float*)d_in[7];
    const float* Wout   = (const float*)d_in[8];
    const float* bout   = (const float*)d_in[9];
    float* out = (float*)d_out;

    cudaFuncSetAttribute(lstm_mma_kernel<1>, cudaFuncAttributeMaxDynamicSharedMemorySize, SMEM_DYN);
    cudaFuncSetAttribute(lstm_mma_kernel<2>, cudaFuncAttributeMaxDynamicSharedMemorySize, SMEM_DYN);

    zero_state_kernel<<<(BATCH * UNITS + 255) / 256, 256>>>();
    prepack_kernel<<<N4, 256>>>(W1, U1, b1, W2, U2, b2);
    gather_kernel<<<ROWS, 128>>>(tokens, emb);
    pregemm_kernel<<<dim3(N4 / 128, ROWS / 128), 256>>>();

    for (int t = 0; t < SEQ; t++) {
        lstm_mma_kernel<1><<<dim3(16, 8), 256, SMEM_DYN>>>(t);
        lstm_mma_kernel<2><<<dim3(16, 8), 256, SMEM_DYN>>>(t);
    }
    out_kernel<<<(BATCH * 32 + 255) / 256, 256>>>(Wout, bout, out, SEQ & 1);
}